// round 16
// baseline (speedup 1.0000x reference)
#include <cuda_runtime.h>
#include <math.h>
#include <stdint.h>

#define BB 2
#define LL 384
#define DD 256
#define HH 8
#define DHH 32
#define FULLM 0xffffffffu

#define SCALE 0.17677669529663687f   // 1/sqrt(32)
#define INV_SCALE 5.656854249492381f

// Scratch (device globals — no allocation allowed). 16B-aligned: float4 access.
__device__ __align__(16) float g_KP[BB*HH*LL*DHH];   // [b][h][l][dh]
__device__ __align__(16) float g_VP[BB*HH*LL*DHH];   // [b][h][l][dh]
__device__ __align__(16) float g_QU[BB*LL*DD];       // [b][l][h*32+dh]  (q + u)
__device__ __align__(16) float g_QV[BB*LL*DD];       // [b][l][h*32+dh]  (q + v)
__device__ __align__(16) float g_W [BB*LL*HH*DD];    // [b][q][h][d]
__device__ __align__(16) float g_CCP[BB*LL*HH];      // [bq][h]  (q+v).br
__device__ __align__(16) float g_AC[BB*HH*LL*LL];    // [b][h][q][k]  AC + ccp - pm/scale
__device__ __align__(16) float g_SC[BB*HH*LL*LL];    // [b][h][q][k]  scores -> probs

__device__ __forceinline__ uint32_t f2tf(float f) {
    uint32_t r;
    asm("cvt.rna.tf32.f32 %0, %1;" : "=r"(r) : "f"(f));
    return r;
}

#define MMA_TF32(d, a0, a1, a2, a3, b0, b1) \
    asm volatile("mma.sync.aligned.m16n8k8.row.col.f32.tf32.tf32.f32 " \
        "{%0,%1,%2,%3}, {%4,%5,%6,%7}, {%8,%9}, {%0,%1,%2,%3};" \
        : "+f"(d[0]), "+f"(d[1]), "+f"(d[2]), "+f"(d[3]) \
        : "r"(a0), "r"(a1), "r"(a2), "r"(a3), "r"(b0), "r"(b1))

// ---------------------------------------------------------------------------
// Kernel 1: fused Q/K/V projections.  out = X @ W.T + b  (M=768, N=256, K=256)
// ---------------------------------------------------------------------------
__global__ void __launch_bounds__(256) proj_kernel(
    const float* __restrict__ key,   const float* __restrict__ query,
    const float* __restrict__ value,
    const float* __restrict__ Wk, const float* __restrict__ bk,
    const float* __restrict__ Wq, const float* __restrict__ bq,
    const float* __restrict__ Wv, const float* __restrict__ bv,
    const float* __restrict__ u,  const float* __restrict__ vvec)
{
    const int z = blockIdx.z;
    const float* X    = (z == 0) ? key : (z == 1) ? query : value;
    const float* Wt   = (z == 0) ? Wk  : (z == 1) ? Wq    : Wv;
    const float* bias = (z == 0) ? bk  : (z == 1) ? bq    : bv;

    const int m0 = blockIdx.x * 32;
    const int n0 = blockIdx.y * 32;
    const int tid = threadIdx.x;
    const int tx = tid % 8, ty = tid / 8;

    __shared__ float a_sm[32 * 65];   // [row][k]
    __shared__ float b_sm[64 * 36];   // [k][n]

    float acc[4] = {};

    const int lr = tid / 16;
    const int lc = (tid % 16) * 4;

    for (int kt = 0; kt < DD; kt += 64) {
        {
            float4 va = *(const float4*)(X + (m0 + lr) * DD + kt + lc);
            float* d0 = a_sm + lr * 65 + lc;
            d0[0] = va.x; d0[1] = va.y; d0[2] = va.z; d0[3] = va.w;
            float4 vb = *(const float4*)(X + (m0 + lr + 16) * DD + kt + lc);
            float* d1 = a_sm + (lr + 16) * 65 + lc;
            d1[0] = vb.x; d1[1] = vb.y; d1[2] = vb.z; d1[3] = vb.w;
        }
        #pragma unroll
        for (int j = 0; j < 2; j++) {
            int nr = lr + 16 * j;
            float4 vb = *(const float4*)(Wt + (n0 + nr) * DD + kt + lc);
            b_sm[(lc + 0) * 36 + nr] = vb.x;
            b_sm[(lc + 1) * 36 + nr] = vb.y;
            b_sm[(lc + 2) * 36 + nr] = vb.z;
            b_sm[(lc + 3) * 36 + nr] = vb.w;
        }
        __syncthreads();
        #pragma unroll
        for (int k = 0; k < 64; k++) {
            float a0 = a_sm[ty * 65 + k];
            float4 bf = *(const float4*)(b_sm + k * 36 + tx * 4);
            acc[0] += a0 * bf.x; acc[1] += a0 * bf.y; acc[2] += a0 * bf.z; acc[3] += a0 * bf.w;
        }
        __syncthreads();
    }

    const int m = m0 + ty;
    const int b = m / LL, l = m % LL;
    #pragma unroll
    for (int j = 0; j < 4; j++) {
        int jc = n0 + tx * 4 + j;
        float val = acc[j] + bias[jc];
        int h = jc / DHH, dh = jc % DHH;
        if (z == 0) {
            g_KP[((b * HH + h) * LL + l) * DHH + dh] = val;
        } else if (z == 2) {
            g_VP[((b * HH + h) * LL + l) * DHH + dh] = val;
        } else {
            g_QU[m * DD + jc] = val + u[jc];
            g_QV[m * DD + jc] = val + vvec[jc];
        }
    }
}

// ---------------------------------------------------------------------------
// Kernel 2: W[b,q,h,:] = sum_dh QV[b,q,h,dh] * Wr[h*32+dh, :] ; also g_CCP.
// ---------------------------------------------------------------------------
__global__ void __launch_bounds__(256) w_kernel(const float* __restrict__ Wr,
                                               const float* __restrict__ br)
{
    const int h  = blockIdx.z;
    const int m0 = blockIdx.x * 64;
    const int n0 = blockIdx.y * 64;
    const int tid = threadIdx.x;
    const int tx = tid % 16, ty = tid / 16;

    __shared__ float a_sm[64 * 33];
    __shared__ float b_sm[32 * 68];

    {
        int r = tid / 4, cb = (tid % 4) * 8;
        #pragma unroll
        for (int cc = 0; cc < 8; cc += 4) {
            float4 va = *(const float4*)(g_QV + (m0 + r) * DD + h * DHH + cb + cc);
            float* dst = a_sm + r * 33 + cb + cc;
            dst[0] = va.x; dst[1] = va.y; dst[2] = va.z; dst[3] = va.w;
        }
    }
    {
        int k = tid / 8, cb = (tid % 8) * 8;
        #pragma unroll
        for (int cc = 0; cc < 8; cc += 4) {
            float4 vb = *(const float4*)(Wr + (h * DHH + k) * DD + n0 + cb + cc);
            *(float4*)(b_sm + k * 68 + cb + cc) = vb;
        }
    }
    __syncthreads();

    if (blockIdx.y == 0 && tid < 64) {
        float s = 0.f;
        #pragma unroll
        for (int d = 0; d < DHH; d++)
            s += a_sm[tid * 33 + d] * br[h * DHH + d];
        g_CCP[(m0 + tid) * HH + h] = s;
    }

    float acc[4][4] = {};
    #pragma unroll
    for (int k = 0; k < 32; k++) {
        float a0 = a_sm[(ty * 4 + 0) * 33 + k];
        float a1 = a_sm[(ty * 4 + 1) * 33 + k];
        float a2 = a_sm[(ty * 4 + 2) * 33 + k];
        float a3 = a_sm[(ty * 4 + 3) * 33 + k];
        float4 bf = *(const float4*)(b_sm + k * 68 + tx * 4);
        acc[0][0] += a0 * bf.x; acc[0][1] += a0 * bf.y; acc[0][2] += a0 * bf.z; acc[0][3] += a0 * bf.w;
        acc[1][0] += a1 * bf.x; acc[1][1] += a1 * bf.y; acc[1][2] += a1 * bf.z; acc[1][3] += a1 * bf.w;
        acc[2][0] += a2 * bf.x; acc[2][1] += a2 * bf.y; acc[2][2] += a2 * bf.z; acc[2][3] += a2 * bf.w;
        acc[3][0] += a3 * bf.x; acc[3][1] += a3 * bf.y; acc[3][2] += a3 * bf.z; acc[3][3] += a3 * bf.w;
    }

    #pragma unroll
    for (int i = 0; i < 4; i++) {
        int bq = m0 + ty * 4 + i;
        #pragma unroll
        for (int j = 0; j < 4; j++) {
            g_W[((size_t)bq * HH + h) * DD + n0 + tx * 4 + j] = acc[i][j];
        }
    }
}

// ---------------------------------------------------------------------------
// Kernel 2b: g_AC[b,h,q,k] = QU(q,h,:).KP(h,k,:) + ccp[q,h] - pm[k]*INV_SCALE
// ---------------------------------------------------------------------------
__global__ void __launch_bounds__(256) ac_kernel(const float* __restrict__ key_mask)
{
    const int bh = blockIdx.z;
    const int b = bh / HH, h = bh % HH;
    const int q0 = blockIdx.x * 64;
    const int k0 = blockIdx.y * 64;
    const int tid = threadIdx.x;
    const int tx = tid % 16, ty = tid / 16;

    __shared__ float a_sm[64 * 33];   // [q][d]
    __shared__ float b_sm[32 * 68];   // [d][k]

    {
        int r = tid / 4, cb = (tid % 4) * 8;
        #pragma unroll
        for (int cc = 0; cc < 8; cc += 4) {
            float4 va = *(const float4*)(g_QU + ((b * LL + q0 + r)) * DD + h * DHH + cb + cc);
            float* dst = a_sm + r * 33 + cb + cc;
            dst[0] = va.x; dst[1] = va.y; dst[2] = va.z; dst[3] = va.w;
        }
    }
    {
        int r = tid / 4, cb = (tid % 4) * 8;
        #pragma unroll
        for (int cc = 0; cc < 8; cc += 4) {
            float4 vb = *(const float4*)(g_KP + ((size_t)(b * HH + h) * LL + k0 + r) * DHH + cb + cc);
            b_sm[(cb + cc + 0) * 68 + r] = vb.x;
            b_sm[(cb + cc + 1) * 68 + r] = vb.y;
            b_sm[(cb + cc + 2) * 68 + r] = vb.z;
            b_sm[(cb + cc + 3) * 68 + r] = vb.w;
        }
    }
    __syncthreads();

    float acc[4][4] = {};
    #pragma unroll
    for (int k = 0; k < 32; k++) {
        float a0 = a_sm[(ty * 4 + 0) * 33 + k];
        float a1 = a_sm[(ty * 4 + 1) * 33 + k];
        float a2 = a_sm[(ty * 4 + 2) * 33 + k];
        float a3 = a_sm[(ty * 4 + 3) * 33 + k];
        float4 bf = *(const float4*)(b_sm + k * 68 + tx * 4);
        acc[0][0] += a0 * bf.x; acc[0][1] += a0 * bf.y; acc[0][2] += a0 * bf.z; acc[0][3] += a0 * bf.w;
        acc[1][0] += a1 * bf.x; acc[1][1] += a1 * bf.y; acc[1][2] += a1 * bf.z; acc[1][3] += a1 * bf.w;
        acc[2][0] += a2 * bf.x; acc[2][1] += a2 * bf.y; acc[2][2] += a2 * bf.z; acc[2][3] += a2 * bf.w;
        acc[3][0] += a3 * bf.x; acc[3][1] += a3 * bf.y; acc[3][2] += a3 * bf.z; acc[3][3] += a3 * bf.w;
    }

    #pragma unroll
    for (int i = 0; i < 4; i++) {
        int qg = q0 + ty * 4 + i;
        float ccp = g_CCP[(b * LL + qg) * HH + h];
        #pragma unroll
        for (int j = 0; j < 4; j++) {
            int kg = k0 + tx * 4 + j;
            float pm = (1.0f - key_mask[b * LL + kg]) * 1e15f;
            g_AC[((size_t)bh * LL + qg) * LL + kg] = acc[i][j] + ccp - pm * INV_SCALE;
        }
    }
}

// ---------------------------------------------------------------------------
// Kernel 3: score3 — 3xTF32 tensor-core B_D.
// Block per (q,b); warp owns 48 k = 3 m16 tiles; S[48k x 8h] = pos @ W^T.
// A (pos) straight from GMEM as mma fragments; W split hi/lo tf32 in smem.
// D = Ahi*Bhi + Ahi*Blo + Alo*Bhi  (~fp32 accuracy).
// Epilogue: per-warp smem transpose, AC merge, coalesced STG.128.
// ---------------------------------------------------------------------------
#define WPAD 260   // (h*260 + d) % 32 = (4h + d) % 32 -> conflict-free B frags

__global__ void __launch_bounds__(256) score3_kernel(const float* __restrict__ pos)
{
    __shared__ float w_hi[HH * WPAD];
    __shared__ float w_lo[HH * WPAD];
    __shared__ float tb[HH][16 * 9];   // per-warp transpose buffer

    const int q = blockIdx.x, b = blockIdx.y;
    const int tid = threadIdx.x;
    const int wid = tid >> 5, lane = tid & 31;
    const int r  = lane >> 2;   // groupID: A row / B col(head) / D row
    const int cL = lane & 3;    // threadID_in_group: A col / B row(k)

    // Split W(b,q) into tf32 hi/lo
    {
        const float* wrow = g_W + ((size_t)(b * LL + q)) * HH * DD;
        for (int j = tid; j < HH * DD; j += 256) {
            float f = wrow[j];
            uint32_t hb = f2tf(f);
            float rem = f - __uint_as_float(hb);
            int h = j >> 8, d = j & 255;
            w_hi[h * WPAD + d] = __uint_as_float(hb);
            w_lo[h * WPAD + d] = __uint_as_float(f2tf(rem));
        }
    }
    __syncthreads();

    const float* pb0 = pos + (((size_t)(b * LL + q)) * LL) * DD + cL;

    #pragma unroll
    for (int t = 0; t < 3; t++) {
        const int k0 = wid * 48 + t * 16;
        const float* pb = pb0 + (size_t)(k0 + r) * DD;
        float dacc[4] = {0.f, 0.f, 0.f, 0.f};

        #pragma unroll 4
        for (int c = 0; c < 32; c++) {
            float f0 = pb[c * 8];
            float f1 = pb[8 * DD + c * 8];
            float f2 = pb[c * 8 + 4];
            float f3 = pb[8 * DD + c * 8 + 4];

            uint32_t ah0 = f2tf(f0), ah1 = f2tf(f1), ah2 = f2tf(f2), ah3 = f2tf(f3);
            uint32_t al0 = f2tf(f0 - __uint_as_float(ah0));
            uint32_t al1 = f2tf(f1 - __uint_as_float(ah1));
            uint32_t al2 = f2tf(f2 - __uint_as_float(ah2));
            uint32_t al3 = f2tf(f3 - __uint_as_float(ah3));

            uint32_t bh0 = __float_as_uint(w_hi[r * WPAD + c * 8 + cL]);
            uint32_t bh1 = __float_as_uint(w_hi[r * WPAD + c * 8 + cL + 4]);
            uint32_t bl0 = __float_as_uint(w_lo[r * WPAD + c * 8 + cL]);
            uint32_t bl1 = __float_as_uint(w_lo[r * WPAD + c * 8 + cL + 4]);

            MMA_TF32(dacc, ah0, ah1, ah2, ah3, bh0, bh1);
            MMA_TF32(dacc, ah0, ah1, ah2, ah3, bl0, bl1);
            MMA_TF32(dacc, al0, al1, al2, al3, bh0, bh1);
        }

        // transpose D frags through warp-private smem
        tb[wid][r * 9 + 2 * cL]           = dacc[0];
        tb[wid][r * 9 + 2 * cL + 1]       = dacc[1];
        tb[wid][(r + 8) * 9 + 2 * cL]     = dacc[2];
        tb[wid][(r + 8) * 9 + 2 * cL + 1] = dacc[3];
        __syncwarp();

        // epilogue: lane -> (h = r, 4 consecutive k); AC merge; STG.128
        {
            const int h = r, ks = cL * 4;
            float v0 = tb[wid][(ks + 0) * 9 + h];
            float v1 = tb[wid][(ks + 1) * 9 + h];
            float v2 = tb[wid][(ks + 2) * 9 + h];
            float v3 = tb[wid][(ks + 3) * 9 + h];
            const size_t off = (((size_t)(b * HH + h)) * LL + q) * LL + k0 + ks;
            float4 ac4 = *(const float4*)(g_AC + off);
            float4 o;
            o.x = (v0 + ac4.x) * SCALE;
            o.y = (v1 + ac4.y) * SCALE;
            o.z = (v2 + ac4.z) * SCALE;
            o.w = (v3 + ac4.w) * SCALE;
            *(float4*)(g_SC + off) = o;
        }
        __syncwarp();
    }
}

// ---------------------------------------------------------------------------
// Kernel 4: softmax in-place on g_SC rows. Block per (q,b), warp = head.
// ---------------------------------------------------------------------------
__global__ void __launch_bounds__(256) softmax_kernel()
{
    const int q = blockIdx.x, b = blockIdx.y;
    const int wid = threadIdx.x >> 5, lane = threadIdx.x & 31;

    float* srow = g_SC + (((size_t)(b * HH + wid)) * LL + q) * LL;

    float v[LL / 32];
    float m = -1e30f;
    #pragma unroll
    for (int i = 0; i < LL / 32; i++) {
        v[i] = srow[lane + i * 32];
        m = fmaxf(m, v[i]);
    }
    #pragma unroll
    for (int off = 16; off; off >>= 1)
        m = fmaxf(m, __shfl_xor_sync(FULLM, m, off));

    float s = 0.f;
    #pragma unroll
    for (int i = 0; i < LL / 32; i++) {
        v[i] = __expf(v[i] - m);
        s += v[i];
    }
    #pragma unroll
    for (int off = 16; off; off >>= 1)
        s += __shfl_xor_sync(FULLM, s, off);
    const float rinv = 1.0f / s;

    #pragma unroll
    for (int i = 0; i < LL / 32; i++)
        srow[lane + i * 32] = v[i] * rinv;
}

// ---------------------------------------------------------------------------
// Kernel 5: av. out[b,q,h,:] = P[h,q,:] @ V[b,h,:,:]. Tiled for V reuse.
// ---------------------------------------------------------------------------
__global__ void __launch_bounds__(256) av_kernel(float* __restrict__ out)
{
    const int bh = blockIdx.y;
    const int b = bh / HH, h = bh % HH;
    const int q0 = blockIdx.x * 32;
    const int tid = threadIdx.x;
    const int tx = tid % 8, ty = tid / 8;

    __shared__ float p_sm[32 * 68];   // [q][k64]
    __shared__ float v_sm[64 * 32];   // [k][d32]

    float acc[4] = {};

    for (int kc = 0; kc < LL; kc += 64) {
        {
            int r = tid / 8, c = (tid % 8) * 8;
            const float* src = g_SC + (((size_t)bh) * LL + q0 + r) * LL + kc + c;
            float4 va = *(const float4*)(src);
            float4 vb = *(const float4*)(src + 4);
            *(float4*)(p_sm + r * 68 + c)     = va;
            *(float4*)(p_sm + r * 68 + c + 4) = vb;
        }
        {
            int r = tid / 4, c = (tid % 4) * 8;
            const float* src = g_VP + (((size_t)bh) * LL + kc + r) * DHH + c;
            float4 va = *(const float4*)(src);
            float4 vb = *(const float4*)(src + 4);
            *(float4*)(v_sm + r * 32 + c)     = va;
            *(float4*)(v_sm + r * 32 + c + 4) = vb;
        }
        __syncthreads();

        #pragma unroll
        for (int k = 0; k < 64; k++) {
            float p = p_sm[ty * 68 + k];
            float4 v4 = *(const float4*)(v_sm + k * 32 + tx * 4);
            acc[0] += p * v4.x; acc[1] += p * v4.y; acc[2] += p * v4.z; acc[3] += p * v4.w;
        }
        __syncthreads();
    }

    float4 o = make_float4(acc[0], acc[1], acc[2], acc[3]);
    *(float4*)(out + ((size_t)(b * LL + q0 + ty)) * DD + h * DHH + tx * 4) = o;
}

// ---------------------------------------------------------------------------
extern "C" void kernel_launch(void* const* d_in, const int* in_sizes, int n_in,
                              void* d_out, int out_size)
{
    const float* key      = (const float*)d_in[0];
    const float* query    = (const float*)d_in[1];
    const float* value    = (const float*)d_in[2];
    const float* pos      = (const float*)d_in[3];
    const float* key_mask = (const float*)d_in[4];
    const float* Wk = (const float*)d_in[5];
    const float* bk = (const float*)d_in[6];
    const float* Wq = (const float*)d_in[7];
    const float* bq = (const float*)d_in[8];
    const float* Wv = (const float*)d_in[9];
    const float* bv = (const float*)d_in[10];
    const float* Wr = (const float*)d_in[11];
    const float* br = (const float*)d_in[12];
    const float* u  = (const float*)d_in[13];
    const float* v  = (const float*)d_in[14];
    float* out = (float*)d_out;

    proj_kernel<<<dim3(24, 8, 3), 256>>>(key, query, value, Wk, bk, Wq, bq, Wv, bv, u, v);
    w_kernel<<<dim3(12, 4, 8), 256>>>(Wr, br);
    ac_kernel<<<dim3(6, 6, 16), 256>>>(key_mask);
    score3_kernel<<<dim3(LL, BB), 256>>>(pos);
    softmax_kernel<<<dim3(LL, BB), 256>>>();
    av_kernel<<<dim3(12, 16), 256>>>(out);
}

// round 17
// speedup vs baseline: 1.0815x; 1.0815x over previous
#include <cuda_runtime.h>
#include <math.h>
#include <stdint.h>

#define BB 2
#define LL 384
#define DD 256
#define HH 8
#define DHH 32
#define FULLM 0xffffffffu

#define SCALE 0.17677669529663687f   // 1/sqrt(32)
#define INV_SCALE 5.656854249492381f

// Scratch (device globals — no allocation allowed). 16B-aligned: float4 access.
__device__ __align__(16) float g_KP[BB*HH*LL*DHH];   // [b][h][l][dh]
__device__ __align__(16) float g_VP[BB*HH*LL*DHH];   // [b][h][l][dh]
__device__ __align__(16) float g_QU[BB*LL*DD];       // [b][l][h*32+dh]  (q + u)
__device__ __align__(16) float g_QV[BB*LL*DD];       // [b][l][h*32+dh]  (q + v)
__device__ __align__(16) float g_W [BB*LL*HH*DD];    // [b][q][h][d]
__device__ __align__(16) float g_CCP[BB*LL*HH];      // [bq][h]  (q+v).br
__device__ __align__(16) float g_AC[BB*HH*LL*LL];    // [b][h][q][k]  AC + ccp - pm/scale
__device__ __align__(16) float g_SC[BB*HH*LL*LL];    // [b][h][q][k]  raw scores

// f32x2 packed helpers
__device__ __forceinline__ unsigned long long pk2(float lo, float hi) {
    unsigned long long r;
    asm("mov.b64 %0, {%1, %2};" : "=l"(r) : "f"(lo), "f"(hi));
    return r;
}
__device__ __forceinline__ unsigned long long mul2(unsigned long long a, unsigned long long b) {
    unsigned long long r;
    asm("mul.rn.f32x2 %0, %1, %2;" : "=l"(r) : "l"(a), "l"(b));
    return r;
}
__device__ __forceinline__ unsigned long long fma2(unsigned long long a, unsigned long long b, unsigned long long c) {
    unsigned long long r;
    asm("fma.rn.f32x2 %0, %1, %2, %3;" : "=l"(r) : "l"(a), "l"(b), "l"(c));
    return r;
}
__device__ __forceinline__ float upk_sum(unsigned long long v) {
    float lo, hi;
    asm("mov.b64 {%0, %1}, %2;" : "=f"(lo), "=f"(hi) : "l"(v));
    return lo + hi;
}

// ---------------------------------------------------------------------------
// Kernel 1: fused Q/K/V projections.  out = X @ W.T + b  (M=768, N=256, K=256)
// ---------------------------------------------------------------------------
__global__ void __launch_bounds__(256) proj_kernel(
    const float* __restrict__ key,   const float* __restrict__ query,
    const float* __restrict__ value,
    const float* __restrict__ Wk, const float* __restrict__ bk,
    const float* __restrict__ Wq, const float* __restrict__ bq,
    const float* __restrict__ Wv, const float* __restrict__ bv,
    const float* __restrict__ u,  const float* __restrict__ vvec)
{
    const int z = blockIdx.z;
    const float* X    = (z == 0) ? key : (z == 1) ? query : value;
    const float* Wt   = (z == 0) ? Wk  : (z == 1) ? Wq    : Wv;
    const float* bias = (z == 0) ? bk  : (z == 1) ? bq    : bv;

    const int m0 = blockIdx.x * 32;
    const int n0 = blockIdx.y * 32;
    const int tid = threadIdx.x;
    const int tx = tid % 8, ty = tid / 8;

    __shared__ float a_sm[32 * 65];   // [row][k]
    __shared__ float b_sm[64 * 36];   // [k][n]

    float acc[4] = {};

    const int lr = tid / 16;
    const int lc = (tid % 16) * 4;

    for (int kt = 0; kt < DD; kt += 64) {
        {
            float4 va = *(const float4*)(X + (m0 + lr) * DD + kt + lc);
            float* d0 = a_sm + lr * 65 + lc;
            d0[0] = va.x; d0[1] = va.y; d0[2] = va.z; d0[3] = va.w;
            float4 vb = *(const float4*)(X + (m0 + lr + 16) * DD + kt + lc);
            float* d1 = a_sm + (lr + 16) * 65 + lc;
            d1[0] = vb.x; d1[1] = vb.y; d1[2] = vb.z; d1[3] = vb.w;
        }
        #pragma unroll
        for (int j = 0; j < 2; j++) {
            int nr = lr + 16 * j;
            float4 vb = *(const float4*)(Wt + (n0 + nr) * DD + kt + lc);
            b_sm[(lc + 0) * 36 + nr] = vb.x;
            b_sm[(lc + 1) * 36 + nr] = vb.y;
            b_sm[(lc + 2) * 36 + nr] = vb.z;
            b_sm[(lc + 3) * 36 + nr] = vb.w;
        }
        __syncthreads();
        #pragma unroll
        for (int k = 0; k < 64; k++) {
            float a0 = a_sm[ty * 65 + k];
            float4 bf = *(const float4*)(b_sm + k * 36 + tx * 4);
            acc[0] += a0 * bf.x; acc[1] += a0 * bf.y; acc[2] += a0 * bf.z; acc[3] += a0 * bf.w;
        }
        __syncthreads();
    }

    const int m = m0 + ty;
    const int b = m / LL, l = m % LL;
    #pragma unroll
    for (int j = 0; j < 4; j++) {
        int jc = n0 + tx * 4 + j;
        float val = acc[j] + bias[jc];
        int h = jc / DHH, dh = jc % DHH;
        if (z == 0) {
            g_KP[((b * HH + h) * LL + l) * DHH + dh] = val;
        } else if (z == 2) {
            g_VP[((b * HH + h) * LL + l) * DHH + dh] = val;
        } else {
            g_QU[m * DD + jc] = val + u[jc];
            g_QV[m * DD + jc] = val + vvec[jc];
        }
    }
}

// ---------------------------------------------------------------------------
// Kernel 2: W[b,q,h,:] = sum_dh QV[b,q,h,dh] * Wr[h*32+dh, :] ; also g_CCP.
// ---------------------------------------------------------------------------
__global__ void __launch_bounds__(256) w_kernel(const float* __restrict__ Wr,
                                               const float* __restrict__ br)
{
    const int h  = blockIdx.z;
    const int m0 = blockIdx.x * 64;
    const int n0 = blockIdx.y * 64;
    const int tid = threadIdx.x;
    const int tx = tid % 16, ty = tid / 16;

    __shared__ float a_sm[64 * 33];
    __shared__ float b_sm[32 * 68];

    {
        int r = tid / 4, cb = (tid % 4) * 8;
        #pragma unroll
        for (int cc = 0; cc < 8; cc += 4) {
            float4 va = *(const float4*)(g_QV + (m0 + r) * DD + h * DHH + cb + cc);
            float* dst = a_sm + r * 33 + cb + cc;
            dst[0] = va.x; dst[1] = va.y; dst[2] = va.z; dst[3] = va.w;
        }
    }
    {
        int k = tid / 8, cb = (tid % 8) * 8;
        #pragma unroll
        for (int cc = 0; cc < 8; cc += 4) {
            float4 vb = *(const float4*)(Wr + (h * DHH + k) * DD + n0 + cb + cc);
            *(float4*)(b_sm + k * 68 + cb + cc) = vb;
        }
    }
    __syncthreads();

    if (blockIdx.y == 0 && tid < 64) {
        float s = 0.f;
        #pragma unroll
        for (int d = 0; d < DHH; d++)
            s += a_sm[tid * 33 + d] * br[h * DHH + d];
        g_CCP[(m0 + tid) * HH + h] = s;
    }

    float acc[4][4] = {};
    #pragma unroll
    for (int k = 0; k < 32; k++) {
        float a0 = a_sm[(ty * 4 + 0) * 33 + k];
        float a1 = a_sm[(ty * 4 + 1) * 33 + k];
        float a2 = a_sm[(ty * 4 + 2) * 33 + k];
        float a3 = a_sm[(ty * 4 + 3) * 33 + k];
        float4 bf = *(const float4*)(b_sm + k * 68 + tx * 4);
        acc[0][0] += a0 * bf.x; acc[0][1] += a0 * bf.y; acc[0][2] += a0 * bf.z; acc[0][3] += a0 * bf.w;
        acc[1][0] += a1 * bf.x; acc[1][1] += a1 * bf.y; acc[1][2] += a1 * bf.z; acc[1][3] += a1 * bf.w;
        acc[2][0] += a2 * bf.x; acc[2][1] += a2 * bf.y; acc[2][2] += a2 * bf.z; acc[2][3] += a2 * bf.w;
        acc[3][0] += a3 * bf.x; acc[3][1] += a3 * bf.y; acc[3][2] += a3 * bf.z; acc[3][3] += a3 * bf.w;
    }

    #pragma unroll
    for (int i = 0; i < 4; i++) {
        int bq = m0 + ty * 4 + i;
        #pragma unroll
        for (int j = 0; j < 4; j++) {
            g_W[((size_t)bq * HH + h) * DD + n0 + tx * 4 + j] = acc[i][j];
        }
    }
}

// ---------------------------------------------------------------------------
// Kernel 2b: g_AC[b,h,q,k] = QU(q,h,:).KP(h,k,:) + ccp[q,h] - pm[k]*INV_SCALE
// ---------------------------------------------------------------------------
__global__ void __launch_bounds__(256) ac_kernel(const float* __restrict__ key_mask)
{
    const int bh = blockIdx.z;
    const int b = bh / HH, h = bh % HH;
    const int q0 = blockIdx.x * 64;
    const int k0 = blockIdx.y * 64;
    const int tid = threadIdx.x;
    const int tx = tid % 16, ty = tid / 16;

    __shared__ float a_sm[64 * 33];   // [q][d]
    __shared__ float b_sm[32 * 68];   // [d][k]

    {
        int r = tid / 4, cb = (tid % 4) * 8;
        #pragma unroll
        for (int cc = 0; cc < 8; cc += 4) {
            float4 va = *(const float4*)(g_QU + ((b * LL + q0 + r)) * DD + h * DHH + cb + cc);
            float* dst = a_sm + r * 33 + cb + cc;
            dst[0] = va.x; dst[1] = va.y; dst[2] = va.z; dst[3] = va.w;
        }
    }
    {
        int r = tid / 4, cb = (tid % 4) * 8;
        #pragma unroll
        for (int cc = 0; cc < 8; cc += 4) {
            float4 vb = *(const float4*)(g_KP + ((size_t)(b * HH + h) * LL + k0 + r) * DHH + cb + cc);
            b_sm[(cb + cc + 0) * 68 + r] = vb.x;
            b_sm[(cb + cc + 1) * 68 + r] = vb.y;
            b_sm[(cb + cc + 2) * 68 + r] = vb.z;
            b_sm[(cb + cc + 3) * 68 + r] = vb.w;
        }
    }
    __syncthreads();

    float acc[4][4] = {};
    #pragma unroll
    for (int k = 0; k < 32; k++) {
        float a0 = a_sm[(ty * 4 + 0) * 33 + k];
        float a1 = a_sm[(ty * 4 + 1) * 33 + k];
        float a2 = a_sm[(ty * 4 + 2) * 33 + k];
        float a3 = a_sm[(ty * 4 + 3) * 33 + k];
        float4 bf = *(const float4*)(b_sm + k * 68 + tx * 4);
        acc[0][0] += a0 * bf.x; acc[0][1] += a0 * bf.y; acc[0][2] += a0 * bf.z; acc[0][3] += a0 * bf.w;
        acc[1][0] += a1 * bf.x; acc[1][1] += a1 * bf.y; acc[1][2] += a1 * bf.z; acc[1][3] += a1 * bf.w;
        acc[2][0] += a2 * bf.x; acc[2][1] += a2 * bf.y; acc[2][2] += a2 * bf.z; acc[2][3] += a2 * bf.w;
        acc[3][0] += a3 * bf.x; acc[3][1] += a3 * bf.y; acc[3][2] += a3 * bf.z; acc[3][3] += a3 * bf.w;
    }

    #pragma unroll
    for (int i = 0; i < 4; i++) {
        int qg = q0 + ty * 4 + i;
        float ccp = g_CCP[(b * LL + qg) * HH + h];
        #pragma unroll
        for (int j = 0; j < 4; j++) {
            int kg = k0 + tx * 4 + j;
            float pm = (1.0f - key_mask[b * LL + kg]) * 1e15f;
            g_AC[((size_t)bh * LL + qg) * LL + kg] = acc[i][j] + ccp - pm * INV_SCALE;
        }
    }
}

// ---------------------------------------------------------------------------
// Kernel 3: score2b. Block per (q,b). Warp = (k-range 0..3, d-half 0..1);
// lane owns 4 d. Pos read ONCE (1 coalesced LDG.128 per k per warp),
// W2[8][2] packed = 32 regs (occupancy up vs score2's 64). 9-SHFL butterfly.
// d-halves combined in epilogue after one __syncthreads.
// ---------------------------------------------------------------------------
__global__ void __launch_bounds__(256, 3) score2b_kernel(const float* __restrict__ pos)
{
    __shared__ float sbuf[4][2][8][100];   // [krange][dhalf][h][k96 pad100]

    const int q = blockIdx.x, b = blockIdx.y;
    const int tid = threadIdx.x;
    const int wid = tid >> 5, lane = tid & 31;
    const int kr = wid >> 1, dh = wid & 1;
    const int kbase = kr * 96;
    // head index held by this lane after the butterfly
    const int hid = ((lane >> 4) & 1) * 4 + ((lane >> 3) & 1) * 2 + ((lane >> 2) & 1);
    const bool writer = (lane & 3) == 0;

    // W for all 8 heads, this lane's 4-d slice of its d-half, packed f32x2
    unsigned long long W2[8][2];
    {
        const float* wp = g_W + ((size_t)(b * LL + q)) * HH * DD + dh * 128 + lane * 4;
        #pragma unroll
        for (int h = 0; h < 8; h++) {
            float4 wa = *(const float4*)(wp + h * DD);
            W2[h][0] = pk2(wa.x, wa.y);
            W2[h][1] = pk2(wa.z, wa.w);
        }
    }

    const float* prow = pos + (((size_t)(b * LL + q)) * LL + kbase) * DD + dh * 128 + lane * 4;

    #pragma unroll 2
    for (int kl = 0; kl < 96; kl++) {
        float4 p = *(const float4*)(prow);
        prow += DD;
        unsigned long long P0 = pk2(p.x, p.y);
        unsigned long long P1 = pk2(p.z, p.w);

        float r[8];
        #pragma unroll
        for (int h = 0; h < 8; h++) {
            unsigned long long a = mul2(P0, W2[h][0]);
            a = fma2(P1, W2[h][1], a);
            r[h] = upk_sum(a);
        }

        // 9-SHFL butterfly: reduce 8 head-sums over 32 lanes
        const bool hi16 = (lane & 16) != 0;
        float t0 = hi16 ? r[0] : r[4];
        float t1 = hi16 ? r[1] : r[5];
        float t2 = hi16 ? r[2] : r[6];
        float t3 = hi16 ? r[3] : r[7];
        t0 = __shfl_xor_sync(FULLM, t0, 16);
        t1 = __shfl_xor_sync(FULLM, t1, 16);
        t2 = __shfl_xor_sync(FULLM, t2, 16);
        t3 = __shfl_xor_sync(FULLM, t3, 16);
        float s0 = (hi16 ? r[4] : r[0]) + t0;
        float s1 = (hi16 ? r[5] : r[1]) + t1;
        float s2 = (hi16 ? r[6] : r[2]) + t2;
        float s3 = (hi16 ? r[7] : r[3]) + t3;

        const bool hi8 = (lane & 8) != 0;
        float u0 = hi8 ? s0 : s2;
        float u1 = hi8 ? s1 : s3;
        u0 = __shfl_xor_sync(FULLM, u0, 8);
        u1 = __shfl_xor_sync(FULLM, u1, 8);
        float v0 = (hi8 ? s2 : s0) + u0;
        float v1 = (hi8 ? s3 : s1) + u1;

        const bool hi4 = (lane & 4) != 0;
        float z = hi4 ? v0 : v1;
        z = __shfl_xor_sync(FULLM, z, 4);
        float f = (hi4 ? v1 : v0) + z;

        f += __shfl_xor_sync(FULLM, f, 2);
        f += __shfl_xor_sync(FULLM, f, 1);

        if (writer) sbuf[kr][dh][hid][kl] = f;
    }
    __syncthreads();

    // epilogue: warp = head; combine d-halves, AC merge, coalesced STG
    {
        const int h = wid;
        const size_t rowoff = (((size_t)(b * HH + h)) * LL + q) * LL;
        #pragma unroll
        for (int i = 0; i < 12; i++) {
            int k = lane + 32 * i;
            int kr2 = k / 96, kl2 = k % 96;
            float s = sbuf[kr2][0][h][kl2] + sbuf[kr2][1][h][kl2];
            g_SC[rowoff + k] = (s + g_AC[rowoff + k]) * SCALE;
        }
    }
}

// ---------------------------------------------------------------------------
// Kernel 4: fused softmax + attn@V.  Block = (q-tile 32, bh).
// P rows staged in dynamic smem, softmax in place, then P @ V tiled.
// ---------------------------------------------------------------------------
#define PST 388                     // padded P row stride (floats), %4==0
#define AV_SMEM ((32 * PST + 64 * 32) * 4)

__global__ void __launch_bounds__(256) av_kernel(float* __restrict__ out)
{
    extern __shared__ __align__(16) float dsm[];
    float* p_sm = dsm;              // [32][PST]
    float* v_sm = dsm + 32 * PST;   // [64][32]

    const int bh = blockIdx.y;
    const int b = bh / HH, h = bh % HH;
    const int q0 = blockIdx.x * 32;
    const int tid = threadIdx.x;
    const int wid = tid >> 5, lane = tid & 31;
    const int tx = tid % 8, ty = tid / 8;

    // load P: 32 rows x 384 = 3072 float4 slots; 12 per thread
    {
        const float4* src = (const float4*)(g_SC + (((size_t)bh) * LL + q0) * LL);
        #pragma unroll
        for (int i = 0; i < 12; i++) {
            int idx = tid + i * 256;
            int row = idx / 96, c4 = idx % 96;
            *(float4*)(p_sm + row * PST + c4 * 4) = src[row * 96 + c4];
        }
    }
    __syncthreads();

    // softmax: warp handles rows 4*wid .. 4*wid+3
    #pragma unroll
    for (int rr = 0; rr < 4; rr++) {
        float* row = p_sm + (wid * 4 + rr) * PST;
        float v[12];
        float m = -1e30f;
        #pragma unroll
        for (int i = 0; i < 12; i++) {
            v[i] = row[lane + i * 32];
            m = fmaxf(m, v[i]);
        }
        #pragma unroll
        for (int off = 16; off; off >>= 1)
            m = fmaxf(m, __shfl_xor_sync(FULLM, m, off));
        float s = 0.f;
        #pragma unroll
        for (int i = 0; i < 12; i++) {
            v[i] = __expf(v[i] - m);
            s += v[i];
        }
        #pragma unroll
        for (int off = 16; off; off >>= 1)
            s += __shfl_xor_sync(FULLM, s, off);
        const float rinv = 1.0f / s;
        #pragma unroll
        for (int i = 0; i < 12; i++)
            row[lane + i * 32] = v[i] * rinv;
    }
    __syncthreads();

    // P @ V, tiled over k
    float acc[4] = {};
    for (int kc = 0; kc < LL; kc += 64) {
        {
            int r = tid / 4, c = (tid % 4) * 8;
            const float* src = g_VP + (((size_t)bh) * LL + kc + r) * DHH + c;
            float4 va = *(const float4*)(src);
            float4 vb = *(const float4*)(src + 4);
            *(float4*)(v_sm + r * 32 + c)     = va;
            *(float4*)(v_sm + r * 32 + c + 4) = vb;
        }
        __syncthreads();

        #pragma unroll
        for (int k = 0; k < 64; k++) {
            float p = p_sm[ty * PST + kc + k];
            float4 v4 = *(const float4*)(v_sm + k * 32 + tx * 4);
            acc[0] += p * v4.x; acc[1] += p * v4.y; acc[2] += p * v4.z; acc[3] += p * v4.w;
        }
        __syncthreads();
    }

    float4 o = make_float4(acc[0], acc[1], acc[2], acc[3]);
    *(float4*)(out + ((size_t)(b * LL + q0 + ty)) * DD + h * DHH + tx * 4) = o;
}

// ---------------------------------------------------------------------------
extern "C" void kernel_launch(void* const* d_in, const int* in_sizes, int n_in,
                              void* d_out, int out_size)
{
    const float* key      = (const float*)d_in[0];
    const float* query    = (const float*)d_in[1];
    const float* value    = (const float*)d_in[2];
    const float* pos      = (const float*)d_in[3];
    const float* key_mask = (const float*)d_in[4];
    const float* Wk = (const float*)d_in[5];
    const float* bk = (const float*)d_in[6];
    const float* Wq = (const float*)d_in[7];
    const float* bq = (const float*)d_in[8];
    const float* Wv = (const float*)d_in[9];
    const float* bv = (const float*)d_in[10];
    const float* Wr = (const float*)d_in[11];
    const float* br = (const float*)d_in[12];
    const float* u  = (const float*)d_in[13];
    const float* v  = (const float*)d_in[14];
    float* out = (float*)d_out;

    cudaFuncSetAttribute(av_kernel, cudaFuncAttributeMaxDynamicSharedMemorySize, AV_SMEM);

    proj_kernel<<<dim3(24, 8, 3), 256>>>(key, query, value, Wk, bk, Wq, bq, Wv, bv, u, v);
    w_kernel<<<dim3(12, 4, 8), 256>>>(Wr, br);
    ac_kernel<<<dim3(6, 6, 16), 256>>>(key_mask);
    score2b_kernel<<<dim3(LL, BB), 256>>>(pos);
    av_kernel<<<dim3(12, 16), 256, AV_SMEM>>>(out);
}